// round 4
// baseline (speedup 1.0000x reference)
#include <cuda_runtime.h>
#include <math.h>

#define NIMG 20
#define B_ 4
#define L_ 5
#define CIN 64
#define H_ 256
#define W_ 128

// ---------------- scratch (alloc-free rule: __device__ globals) ----------------
__device__ float g_neigh[(size_t)NIMG*CIN*H_*W_];   // 167.8 MB
__device__ float g_c1[(size_t)NIMG*32*128*64];      // 21 MB
__device__ float g_c2[(size_t)NIMG*64*64*32];      // 10.5 MB
__device__ float g_c3[(size_t)NIMG*64*32*16];      // 2.6 MB
__device__ float g_pool[NIMG*64];
__device__ float g_keys[NIMG*256];
__device__ float g_q[B_*256];
__device__ float g_attn[B_*L_];

// ---------------- 1) affine grid + bilinear sample (zero pad) ----------------
__global__ void gs_kernel(const float* __restrict__ x, const float* __restrict__ nam) {
    int w   = threadIdx.x;      // 0..127
    int h   = blockIdx.x;       // 0..255
    int img = blockIdx.y;       // 0..19
    int b = img / L_, n = img % L_;
    const float* th = nam + ((size_t)b*L_*L_ + n)*6;   // tmats = nam[:,0] -> nam[b,0,n]
    float t0 = th[0], t1 = th[1], t2 = th[2];
    float t3 = th[3], t4 = th[4], t5 = th[5];

    float gx = (w + 0.5f)*(2.0f/W_) - 1.0f;
    float gy = (h + 0.5f)*(2.0f/H_) - 1.0f;
    float sx = t0*gx + t1*gy + t2;
    float sy = t3*gx + t4*gy + t5;
    float fx = ((sx + 1.0f)*W_ - 1.0f)*0.5f;
    float fy = ((sy + 1.0f)*H_ - 1.0f)*0.5f;
    float x0f = floorf(fx), y0f = floorf(fy);
    int ix0 = (int)x0f, iy0 = (int)y0f;
    int ix1 = ix0 + 1,  iy1 = iy0 + 1;
    float wx1 = fx - x0f, wy1 = fy - y0f;
    float wx0 = 1.0f - wx1, wy0 = 1.0f - wy1;

    bool vx0 = (ix0 >= 0) & (ix0 < W_);
    bool vx1 = (ix1 >= 0) & (ix1 < W_);
    bool vy0 = (iy0 >= 0) & (iy0 < H_);
    bool vy1 = (iy1 >= 0) & (iy1 < H_);
    int cx0 = min(max(ix0, 0), W_-1), cx1 = min(max(ix1, 0), W_-1);
    int cy0 = min(max(iy0, 0), H_-1), cy1 = min(max(iy1, 0), H_-1);

    float w00 = wx0*wy0*((vx0 & vy0) ? 1.0f : 0.0f);
    float w10 = wx1*wy0*((vx1 & vy0) ? 1.0f : 0.0f);
    float w01 = wx0*wy1*((vx0 & vy1) ? 1.0f : 0.0f);
    float w11 = wx1*wy1*((vx1 & vy1) ? 1.0f : 0.0f);

    int o00 = cy0*W_ + cx0, o10 = cy0*W_ + cx1;
    int o01 = cy1*W_ + cx0, o11 = cy1*W_ + cx1;

    const float* base = x + (size_t)img*CIN*H_*W_;
    float* outp = g_neigh + (size_t)img*CIN*H_*W_ + h*W_ + w;
    #pragma unroll 4
    for (int c = 0; c < CIN; c++) {
        const float* pc = base + (size_t)c*H_*W_;
        float v = w00*pc[o00] + w10*pc[o10] + w01*pc[o01] + w11*pc[o11];
        outp[(size_t)c*H_*W_] = v;
    }
}

// ---------------- 2) direct conv 4x4 stride2 pad1 + bias + relu ----------------
// Block: OW*TOH threads, one (img, row-tile). Weights staged transposed so the
// oc dimension is contiguous (float4 broadcast LDS); input tile staged in smem.
template<int IC, int OC, int IH, int IW, int TOH>
__global__ void __launch_bounds__(256) conv_k(const float* __restrict__ in,
                                              const float* __restrict__ wt,
                                              const float* __restrict__ bias,
                                              float* __restrict__ out) {
    constexpr int OH = IH/2, OW = IW/2;
    constexpr int ICC = 4;
    constexpr int ROWS = 2*TOH + 2;
    constexpr int SW = IW + 2;
    constexpr int NT = OW * TOH;

    __shared__ __align__(16) float s_w[ICC][16][OC];
    __shared__ float s_in[ICC][ROWS][SW];

    int img = blockIdx.y;
    int r0  = blockIdx.x * TOH;
    int tid = threadIdx.x;
    int ow  = tid % OW, ohl = tid / OW;

    float acc[OC];
    #pragma unroll
    for (int i = 0; i < OC; i++) acc[i] = 0.0f;

    for (int icb = 0; icb < IC; icb += ICC) {
        __syncthreads();
        // input tile (with zero halo)
        for (int i = tid; i < ICC*ROWS*SW; i += NT) {
            int icl = i / (ROWS*SW); int rem = i % (ROWS*SW);
            int r = rem / SW, col = rem % SW;
            int iy = 2*r0 - 1 + r, ix = col - 1;
            float v = 0.0f;
            if (iy >= 0 && iy < IH && ix >= 0 && ix < IW)
                v = in[(((size_t)img*IC + icb + icl)*IH + iy)*IW + ix];
            s_in[icl][r][col] = v;
        }
        // weights transposed: s_w[icl][ky*4+kx][oc]
        for (int i = tid; i < ICC*16*OC; i += NT) {
            int icl = i / (16*OC); int rem = i % (16*OC);
            int t = rem / OC, oc = rem % OC;
            s_w[icl][t][oc] = wt[((size_t)oc*IC + icb + icl)*16 + t];
        }
        __syncthreads();

        for (int icl = 0; icl < ICC; icl++) {
            #pragma unroll
            for (int ky = 0; ky < 4; ky++) {
                int row = 2*ohl + ky;
                #pragma unroll
                for (int kx = 0; kx < 4; kx++) {
                    float v = s_in[icl][row][2*ow + kx];
                    const float4* wp = (const float4*)&s_w[icl][ky*4 + kx][0];
                    #pragma unroll
                    for (int o4 = 0; o4 < OC/4; o4++) {
                        float4 w4 = wp[o4];
                        acc[4*o4+0] += v * w4.x;
                        acc[4*o4+1] += v * w4.y;
                        acc[4*o4+2] += v * w4.z;
                        acc[4*o4+3] += v * w4.w;
                    }
                }
            }
        }
    }

    int oh = r0 + ohl;
    #pragma unroll
    for (int oc = 0; oc < OC; oc++) {
        float v = acc[oc] + bias[oc];
        out[(((size_t)img*OC + oc)*OH + oh)*OW + ow] = fmaxf(v, 0.0f);
    }
}

// ---------------- 3) spatial mean pool (32x16 = 512) ----------------
__global__ void pool_kernel() {
    int img = blockIdx.x;
    int t = threadIdx.x;            // 256
    int c = t >> 2, q = t & 3;
    const float* p = g_c3 + ((size_t)img*64 + c)*512 + q*128;
    float s = 0.0f;
    for (int i = 0; i < 128; i++) s += p[i];
    __shared__ float sh[256];
    sh[t] = s;
    __syncthreads();
    if (q == 0)
        g_pool[img*64 + c] = (sh[t] + sh[t+1] + sh[t+2] + sh[t+3]) * (1.0f/512.0f);
}

// ---------------- 4) key MLP: 64->256->128->256 ----------------
__global__ void keys_kernel(const float* __restrict__ f1w, const float* __restrict__ f1b,
                            const float* __restrict__ f2w, const float* __restrict__ f2b,
                            const float* __restrict__ f3w, const float* __restrict__ f3b) {
    int img = blockIdx.x;
    int t = threadIdx.x;            // 256
    __shared__ float pooled[64], h1[256], h2[128];
    if (t < 64) pooled[t] = g_pool[img*64 + t];
    __syncthreads();
    {
        float s = f1b[t];
        const float* wr = f1w + (size_t)t*64;
        #pragma unroll 8
        for (int k = 0; k < 64; k++) s += pooled[k]*wr[k];
        h1[t] = fmaxf(s, 0.0f);
    }
    __syncthreads();
    if (t < 128) {
        float s = f2b[t];
        const float* wr = f2w + (size_t)t*256;
        #pragma unroll 8
        for (int k = 0; k < 256; k++) s += h1[k]*wr[k];
        h2[t] = fmaxf(s, 0.0f);
    }
    __syncthreads();
    {
        float s = f3b[t];
        const float* wr = f3w + (size_t)t*128;
        #pragma unroll 8
        for (int k = 0; k < 128; k++) s += h2[k]*wr[k];
        g_keys[img*256 + t] = s;
    }
}

// ---------------- 5) query MLP (img b*5): 64->256->128->32, then q = A qry + b ----------------
__global__ void qry_kernel(const float* __restrict__ f1w, const float* __restrict__ f1b,
                           const float* __restrict__ f2w, const float* __restrict__ f2b,
                           const float* __restrict__ f3w, const float* __restrict__ f3b,
                           const float* __restrict__ aw,  const float* __restrict__ ab) {
    int b = blockIdx.x;
    int img = b * L_;
    int t = threadIdx.x;            // 256
    __shared__ float pooled[64], h1[256], h2[128], qv[32];
    if (t < 64) pooled[t] = g_pool[img*64 + t];
    __syncthreads();
    {
        float s = f1b[t];
        const float* wr = f1w + (size_t)t*64;
        #pragma unroll 8
        for (int k = 0; k < 64; k++) s += pooled[k]*wr[k];
        h1[t] = fmaxf(s, 0.0f);
    }
    __syncthreads();
    if (t < 128) {
        float s = f2b[t];
        const float* wr = f2w + (size_t)t*256;
        #pragma unroll 8
        for (int k = 0; k < 256; k++) s += h1[k]*wr[k];
        h2[t] = fmaxf(s, 0.0f);
    }
    __syncthreads();
    if (t < 32) {
        float s = f3b[t];
        const float* wr = f3w + (size_t)t*128;
        #pragma unroll 8
        for (int k = 0; k < 128; k++) s += h2[k]*wr[k];
        qv[t] = s;   // no relu on last layer
    }
    __syncthreads();
    {
        float s = ab[t];
        const float* wr = aw + (size_t)t*32;
        #pragma unroll 8
        for (int k = 0; k < 32; k++) s += qv[k]*wr[k];
        g_q[b*256 + t] = s;
    }
}

// ---------------- 6) attention logits + softmax over L=5 ----------------
__global__ void attn_kernel() {
    int b = blockIdx.x;
    int t = threadIdx.x;            // 160 = 5 warps
    int n = t >> 5, lane = t & 31;
    __shared__ float logits[L_];
    const float* kp = g_keys + ((size_t)b*L_ + n)*256;
    const float* qp = g_q + b*256;
    float s = 0.0f;
    for (int k = lane; k < 256; k += 32) s += kp[k]*qp[k];
    #pragma unroll
    for (int o = 16; o; o >>= 1) s += __shfl_xor_sync(0xffffffff, s, o);
    if (lane == 0) logits[n] = s;
    __syncthreads();
    if (t == 0) {
        float m = logits[0];
        #pragma unroll
        for (int i = 1; i < L_; i++) m = fmaxf(m, logits[i]);
        float e[L_], sum = 0.0f;
        #pragma unroll
        for (int i = 0; i < L_; i++) { e[i] = expf(logits[i] - m); sum += e[i]; }
        #pragma unroll
        for (int i = 0; i < L_; i++) g_attn[b*L_ + i] = e[i] / sum;
    }
}

// ---------------- 7) out[b] = sum_n attn[b,n] * neigh[b,n] ----------------
__global__ void final_kernel(float* __restrict__ out) {
    size_t i = (size_t)blockIdx.x * blockDim.x + threadIdx.x;   // float4 index
    const size_t perimg4 = (size_t)CIN*H_*W_/4;                 // 524288
    int b = (int)(i / perimg4);
    size_t inner = i - (size_t)b*perimg4;
    const float4* nb = (const float4*)g_neigh;
    float a0 = g_attn[b*L_+0], a1 = g_attn[b*L_+1], a2 = g_attn[b*L_+2],
          a3 = g_attn[b*L_+3], a4 = g_attn[b*L_+4];
    float4 v0 = nb[((size_t)(b*L_+0))*perimg4 + inner];
    float4 v1 = nb[((size_t)(b*L_+1))*perimg4 + inner];
    float4 v2 = nb[((size_t)(b*L_+2))*perimg4 + inner];
    float4 v3 = nb[((size_t)(b*L_+3))*perimg4 + inner];
    float4 v4 = nb[((size_t)(b*L_+4))*perimg4 + inner];
    float4 r;
    r.x = a0*v0.x + a1*v1.x + a2*v2.x + a3*v3.x + a4*v4.x;
    r.y = a0*v0.y + a1*v1.y + a2*v2.y + a3*v3.y + a4*v4.y;
    r.z = a0*v0.z + a1*v1.z + a2*v2.z + a3*v3.z + a4*v4.z;
    r.w = a0*v0.w + a1*v1.w + a2*v2.w + a3*v3.w + a4*v4.w;
    ((float4*)out)[i] = r;
}

// ---------------- launch ----------------
extern "C" void kernel_launch(void* const* d_in, const int* in_sizes, int n_in,
                              void* d_out, int out_size) {
    const float* x    = (const float*)d_in[0];
    // d_in[1] = record_len (unused: always L)
    const float* nam  = (const float*)d_in[2];
    const float* w1   = (const float*)d_in[3];
    const float* b1   = (const float*)d_in[4];
    const float* w2   = (const float*)d_in[5];
    const float* b2   = (const float*)d_in[6];
    const float* w3   = (const float*)d_in[7];
    const float* b3   = (const float*)d_in[8];
    const float* kf1w = (const float*)d_in[9];
    const float* kf1b = (const float*)d_in[10];
    const float* kf2w = (const float*)d_in[11];
    const float* kf2b = (const float*)d_in[12];
    const float* kf3w = (const float*)d_in[13];
    const float* kf3b = (const float*)d_in[14];
    const float* qf1w = (const float*)d_in[15];
    const float* qf1b = (const float*)d_in[16];
    const float* qf2w = (const float*)d_in[17];
    const float* qf2b = (const float*)d_in[18];
    const float* qf3w = (const float*)d_in[19];
    const float* qf3b = (const float*)d_in[20];
    const float* aw   = (const float*)d_in[21];
    const float* ab   = (const float*)d_in[22];

    float *p_neigh, *p_c1, *p_c2, *p_c3;
    cudaGetSymbolAddress((void**)&p_neigh, g_neigh);
    cudaGetSymbolAddress((void**)&p_c1, g_c1);
    cudaGetSymbolAddress((void**)&p_c2, g_c2);
    cudaGetSymbolAddress((void**)&p_c3, g_c3);

    gs_kernel<<<dim3(H_, NIMG), W_>>>(x, nam);
    conv_k<64, 32, 256, 128, 4><<<dim3(32, NIMG), 256>>>(p_neigh, w1, b1, p_c1);
    conv_k<32, 64, 128,  64, 8><<<dim3( 8, NIMG), 256>>>(p_c1,    w2, b2, p_c2);
    conv_k<64, 64,  64,  32,16><<<dim3( 2, NIMG), 256>>>(p_c2,    w3, b3, p_c3);
    pool_kernel<<<NIMG, 256>>>();
    keys_kernel<<<NIMG, 256>>>(kf1w, kf1b, kf2w, kf2b, kf3w, kf3b);
    qry_kernel<<<B_, 256>>>(qf1w, qf1b, qf2w, qf2b, qf3w, qf3b, aw, ab);
    attn_kernel<<<B_, 160>>>();
    final_kernel<<<(B_*CIN*H_*W_/4)/256, 256>>>((float*)d_out);
}

// round 8
// speedup vs baseline: 1.4367x; 1.4367x over previous
#include <cuda_runtime.h>
#include <cuda_bf16.h>
#include <mma.h>
#include <math.h>

using namespace nvcuda;

#define NIMG 20
#define B_ 4
#define L_ 5
#define CIN 64
#define H_ 256
#define W_ 128

// ---------------- scratch (alloc-free rule: __device__ globals) ----------------
__device__ float g_neigh[(size_t)NIMG*CIN*H_*W_];   // 167.8 MB
__device__ float g_c1[(size_t)NIMG*32*128*64];      // 21 MB
__device__ float g_c2[(size_t)NIMG*64*64*32];       // 10.5 MB
__device__ float g_c3[(size_t)NIMG*64*32*16];       // 2.6 MB
__device__ float g_pool[NIMG*64];
__device__ float g_keys[NIMG*256];
__device__ float g_q[B_*256];
__device__ float g_attn[B_*L_];
// bf16 weight matrices, layout [K][OC] with k = ic*16 + ky*4 + kx
__device__ __nv_bfloat16 g_wb1[1024*32];
__device__ __nv_bfloat16 g_wb2[512*64];
__device__ __nv_bfloat16 g_wb3[1024*64];

// ---------------- 1) affine grid + bilinear sample (zero pad) ----------------
__global__ void gs_kernel(const float* __restrict__ x, const float* __restrict__ nam) {
    int w   = threadIdx.x;      // 0..127
    int h   = blockIdx.x;       // 0..255
    int img = blockIdx.y;       // 0..19
    int b = img / L_, n = img % L_;
    const float* th = nam + ((size_t)b*L_*L_ + n)*6;   // tmats = nam[:,0] -> nam[b,0,n]
    float t0 = th[0], t1 = th[1], t2 = th[2];
    float t3 = th[3], t4 = th[4], t5 = th[5];

    float gx = (w + 0.5f)*(2.0f/W_) - 1.0f;
    float gy = (h + 0.5f)*(2.0f/H_) - 1.0f;
    float sx = t0*gx + t1*gy + t2;
    float sy = t3*gx + t4*gy + t5;
    float fx = ((sx + 1.0f)*W_ - 1.0f)*0.5f;
    float fy = ((sy + 1.0f)*H_ - 1.0f)*0.5f;
    float x0f = floorf(fx), y0f = floorf(fy);
    int ix0 = (int)x0f, iy0 = (int)y0f;
    int ix1 = ix0 + 1,  iy1 = iy0 + 1;
    float wx1 = fx - x0f, wy1 = fy - y0f;
    float wx0 = 1.0f - wx1, wy0 = 1.0f - wy1;

    bool vx0 = (ix0 >= 0) & (ix0 < W_);
    bool vx1 = (ix1 >= 0) & (ix1 < W_);
    bool vy0 = (iy0 >= 0) & (iy0 < H_);
    bool vy1 = (iy1 >= 0) & (iy1 < H_);
    int cx0 = min(max(ix0, 0), W_-1), cx1 = min(max(ix1, 0), W_-1);
    int cy0 = min(max(iy0, 0), H_-1), cy1 = min(max(iy1, 0), H_-1);

    float w00 = wx0*wy0*((vx0 & vy0) ? 1.0f : 0.0f);
    float w10 = wx1*wy0*((vx1 & vy0) ? 1.0f : 0.0f);
    float w01 = wx0*wy1*((vx0 & vy1) ? 1.0f : 0.0f);
    float w11 = wx1*wy1*((vx1 & vy1) ? 1.0f : 0.0f);

    int o00 = cy0*W_ + cx0, o10 = cy0*W_ + cx1;
    int o01 = cy1*W_ + cx0, o11 = cy1*W_ + cx1;

    const float* base = x + (size_t)img*CIN*H_*W_;
    float* outp = g_neigh + (size_t)img*CIN*H_*W_ + h*W_ + w;
    #pragma unroll 4
    for (int c = 0; c < CIN; c++) {
        const float* pc = base + (size_t)c*H_*W_;
        float v = w00*pc[o00] + w10*pc[o10] + w01*pc[o01] + w11*pc[o11];
        outp[(size_t)c*H_*W_] = v;
    }
}

// ---------------- weight f32 (OC,IC,4,4) -> bf16 [K][OC], k=(ic,ky,kx) ----------------
template<int IC, int OC>
__global__ void wconv_bf16(const float* __restrict__ w, __nv_bfloat16* __restrict__ wb) {
    int i = blockIdx.x*256 + threadIdx.x;          // over K*OC
    if (i >= IC*16*OC) return;
    int k = i / OC, oc = i % OC;
    int ic = k >> 4, t = k & 15;
    wb[i] = __float2bfloat16(w[((size_t)oc*IC + ic)*16 + t]);
}

// ---------------- conv 4x4 stride2 pad1 + bias + relu, WMMA bf16 implicit GEMM ----
// Block: 8 warps compute a 128(M) x OC(N) output tile; M rows = TOH out rows x OW.
// K loop over input channels (16 taps per ic = one k16 step).
template<int IC, int OC, int IH, int IW, int TOH>
__global__ void __launch_bounds__(256) conv_wmma(const float* __restrict__ in,
                                                 const __nv_bfloat16* __restrict__ wb,
                                                 const float* __restrict__ bias,
                                                 float* __restrict__ out) {
    constexpr int OH = IH/2, OW = IW/2;
    constexpr int ROWS = 2*TOH + 2;
    constexpr int SW = IW + 2;
    static_assert(TOH*OW == 128, "M tile must be 128");

    __shared__ float s_rows[ROWS][SW];
    __shared__ __align__(32) __nv_bfloat16 s_a[128][16];
    __shared__ float s_out[128][OC];

    int img = blockIdx.y;
    int oh0 = blockIdx.x * TOH;
    int tid = threadIdx.x;
    int wid = tid >> 5;

    wmma::fragment<wmma::accumulator, 16,16,16, float> acc[OC/16];
    #pragma unroll
    for (int j = 0; j < OC/16; j++) wmma::fill_fragment(acc[j], 0.0f);

    for (int ic = 0; ic < IC; ic++) {
        __syncthreads();
        // stage input row window (zero halo) for this ic
        const float* src = in + ((size_t)img*IC + ic)*IH*IW;
        for (int i = tid; i < ROWS*SW; i += 256) {
            int r = i / SW, c = i % SW;
            int iy = 2*oh0 - 1 + r, ix = c - 1;
            float v = 0.0f;
            if (iy >= 0 && iy < IH && ix >= 0 && ix < IW) v = src[iy*IW + ix];
            s_rows[r][c] = v;
        }
        __syncthreads();
        // build A chunk: 128 x 16 bf16, k = ky*4+kx
        for (int i = tid; i < 128*16; i += 256) {
            int m = i >> 4, k = i & 15;
            int ky = k >> 2, kx = k & 3;
            int ohl = m / OW, ow = m % OW;
            s_a[m][k] = __float2bfloat16(s_rows[2*ohl + ky][2*ow + kx]);
        }
        __syncthreads();
        wmma::fragment<wmma::matrix_a, 16,16,16, __nv_bfloat16, wmma::row_major> fa;
        wmma::load_matrix_sync(fa, &s_a[wid*16][0], 16);
        #pragma unroll
        for (int j = 0; j < OC/16; j++) {
            wmma::fragment<wmma::matrix_b, 16,16,16, __nv_bfloat16, wmma::row_major> fb;
            wmma::load_matrix_sync(fb, wb + (size_t)ic*16*OC + j*16, OC);
            wmma::mma_sync(acc[j], fa, fb, acc[j]);
        }
    }

    __syncthreads();
    #pragma unroll
    for (int j = 0; j < OC/16; j++)
        wmma::store_matrix_sync(&s_out[wid*16][j*16], acc[j], OC, wmma::mem_row_major);
    __syncthreads();
    // epilogue: bias + relu, write channel-major
    for (int i = tid; i < 128*OC; i += 256) {
        int m = i % 128, oc = i / 128;
        int oh = oh0 + m / OW, ow = m % OW;
        float v = s_out[m][oc] + bias[oc];
        out[(((size_t)img*OC + oc)*OH + oh)*OW + ow] = fmaxf(v, 0.0f);
    }
}

// ---------------- 3) spatial mean pool (32x16 = 512) ----------------
__global__ void pool_kernel() {
    int img = blockIdx.x;
    int t = threadIdx.x;            // 256
    int c = t >> 2, q = t & 3;
    const float* p = g_c3 + ((size_t)img*64 + c)*512 + q*128;
    float s = 0.0f;
    for (int i = 0; i < 128; i++) s += p[i];
    __shared__ float sh[256];
    sh[t] = s;
    __syncthreads();
    if (q == 0)
        g_pool[img*64 + c] = (sh[t] + sh[t+1] + sh[t+2] + sh[t+3]) * (1.0f/512.0f);
}

// ---------------- 4) key MLP: 64->256->128->256 ----------------
__global__ void keys_kernel(const float* __restrict__ f1w, const float* __restrict__ f1b,
                            const float* __restrict__ f2w, const float* __restrict__ f2b,
                            const float* __restrict__ f3w, const float* __restrict__ f3b) {
    int img = blockIdx.x;
    int t = threadIdx.x;            // 256
    __shared__ float pooled[64], h1[256], h2[128];
    if (t < 64) pooled[t] = g_pool[img*64 + t];
    __syncthreads();
    {
        float s = f1b[t];
        const float* wr = f1w + (size_t)t*64;
        #pragma unroll 8
        for (int k = 0; k < 64; k++) s += pooled[k]*wr[k];
        h1[t] = fmaxf(s, 0.0f);
    }
    __syncthreads();
    if (t < 128) {
        float s = f2b[t];
        const float* wr = f2w + (size_t)t*256;
        #pragma unroll 8
        for (int k = 0; k < 256; k++) s += h1[k]*wr[k];
        h2[t] = fmaxf(s, 0.0f);
    }
    __syncthreads();
    {
        float s = f3b[t];
        const float* wr = f3w + (size_t)t*128;
        #pragma unroll 8
        for (int k = 0; k < 128; k++) s += h2[k]*wr[k];
        g_keys[img*256 + t] = s;
    }
}

// ---------------- 5) query MLP (img b*5): 64->256->128->32, then q = A qry + b ----------------
__global__ void qry_kernel(const float* __restrict__ f1w, const float* __restrict__ f1b,
                           const float* __restrict__ f2w, const float* __restrict__ f2b,
                           const float* __restrict__ f3w, const float* __restrict__ f3b,
                           const float* __restrict__ aw,  const float* __restrict__ ab) {
    int b = blockIdx.x;
    int img = b * L_;
    int t = threadIdx.x;            // 256
    __shared__ float pooled[64], h1[256], h2[128], qv[32];
    if (t < 64) pooled[t] = g_pool[img*64 + t];
    __syncthreads();
    {
        float s = f1b[t];
        const float* wr = f1w + (size_t)t*64;
        #pragma unroll 8
        for (int k = 0; k < 64; k++) s += pooled[k]*wr[k];
        h1[t] = fmaxf(s, 0.0f);
    }
    __syncthreads();
    if (t < 128) {
        float s = f2b[t];
        const float* wr = f2w + (size_t)t*256;
        #pragma unroll 8
        for (int k = 0; k < 256; k++) s += h1[k]*wr[k];
        h2[t] = fmaxf(s, 0.0f);
    }
    __syncthreads();
    if (t < 32) {
        float s = f3b[t];
        const float* wr = f3w + (size_t)t*128;
        #pragma unroll 8
        for (int k = 0; k < 128; k++) s += h2[k]*wr[k];
        qv[t] = s;   // no relu on last layer
    }
    __syncthreads();
    {
        float s = ab[t];
        const float* wr = aw + (size_t)t*32;
        #pragma unroll 8
        for (int k = 0; k < 32; k++) s += qv[k]*wr[k];
        g_q[b*256 + t] = s;
    }
}

// ---------------- 6) attention logits + softmax over L=5 ----------------
__global__ void attn_kernel() {
    int b = blockIdx.x;
    int t = threadIdx.x;            // 160 = 5 warps
    int n = t >> 5, lane = t & 31;
    __shared__ float logits[L_];
    const float* kp = g_keys + ((size_t)b*L_ + n)*256;
    const float* qp = g_q + b*256;
    float s = 0.0f;
    for (int k = lane; k < 256; k += 32) s += kp[k]*qp[k];
    #pragma unroll
    for (int o = 16; o; o >>= 1) s += __shfl_xor_sync(0xffffffff, s, o);
    if (lane == 0) logits[n] = s;
    __syncthreads();
    if (t == 0) {
        float m = logits[0];
        #pragma unroll
        for (int i = 1; i < L_; i++) m = fmaxf(m, logits[i]);
        float e[L_], sum = 0.0f;
        #pragma unroll
        for (int i = 0; i < L_; i++) { e[i] = expf(logits[i] - m); sum += e[i]; }
        #pragma unroll
        for (int i = 0; i < L_; i++) g_attn[b*L_ + i] = e[i] / sum;
    }
}

// ---------------- 7) out[b] = sum_n attn[b,n] * neigh[b,n] ----------------
__global__ void final_kernel(float* __restrict__ out) {
    size_t i = (size_t)blockIdx.x * blockDim.x + threadIdx.x;   // float4 index
    const size_t perimg4 = (size_t)CIN*H_*W_/4;                 // 524288
    int b = (int)(i / perimg4);
    size_t inner = i - (size_t)b*perimg4;
    const float4* nb = (const float4*)g_neigh;
    float a0 = g_attn[b*L_+0], a1 = g_attn[b*L_+1], a2 = g_attn[b*L_+2],
          a3 = g_attn[b*L_+3], a4 = g_attn[b*L_+4];
    float4 v0 = nb[((size_t)(b*L_+0))*perimg4 + inner];
    float4 v1 = nb[((size_t)(b*L_+1))*perimg4 + inner];
    float4 v2 = nb[((size_t)(b*L_+2))*perimg4 + inner];
    float4 v3 = nb[((size_t)(b*L_+3))*perimg4 + inner];
    float4 v4 = nb[((size_t)(b*L_+4))*perimg4 + inner];
    float4 r;
    r.x = a0*v0.x + a1*v1.x + a2*v2.x + a3*v3.x + a4*v4.x;
    r.y = a0*v0.y + a1*v1.y + a2*v2.y + a3*v3.y + a4*v4.y;
    r.z = a0*v0.z + a1*v1.z + a2*v2.z + a3*v3.z + a4*v4.z;
    r.w = a0*v0.w + a1*v1.w + a2*v2.w + a3*v3.w + a4*v4.w;
    ((float4*)out)[i] = r;
}

// ---------------- launch ----------------
extern "C" void kernel_launch(void* const* d_in, const int* in_sizes, int n_in,
                              void* d_out, int out_size) {
    const float* x    = (const float*)d_in[0];
    // d_in[1] = record_len (unused: always L)
    const float* nam  = (const float*)d_in[2];
    const float* w1   = (const float*)d_in[3];
    const float* b1   = (const float*)d_in[4];
    const float* w2   = (const float*)d_in[5];
    const float* b2   = (const float*)d_in[6];
    const float* w3   = (const float*)d_in[7];
    const float* b3   = (const float*)d_in[8];
    const float* kf1w = (const float*)d_in[9];
    const float* kf1b = (const float*)d_in[10];
    const float* kf2w = (const float*)d_in[11];
    const float* kf2b = (const float*)d_in[12];
    const float* kf3w = (const float*)d_in[13];
    const float* kf3b = (const float*)d_in[14];
    const float* qf1w = (const float*)d_in[15];
    const float* qf1b = (const float*)d_in[16];
    const float* qf2w = (const float*)d_in[17];
    const float* qf2b = (const float*)d_in[18];
    const float* qf3w = (const float*)d_in[19];
    const float* qf3b = (const float*)d_in[20];
    const float* aw   = (const float*)d_in[21];
    const float* ab   = (const float*)d_in[22];

    float *p_neigh, *p_c1, *p_c2, *p_c3;
    __nv_bfloat16 *p_wb1, *p_wb2, *p_wb3;
    cudaGetSymbolAddress((void**)&p_neigh, g_neigh);
    cudaGetSymbolAddress((void**)&p_c1, g_c1);
    cudaGetSymbolAddress((void**)&p_c2, g_c2);
    cudaGetSymbolAddress((void**)&p_c3, g_c3);
    cudaGetSymbolAddress((void**)&p_wb1, g_wb1);
    cudaGetSymbolAddress((void**)&p_wb2, g_wb2);
    cudaGetSymbolAddress((void**)&p_wb3, g_wb3);

    // weight conversion (tiny)
    wconv_bf16<64, 32><<<128, 256>>>(w1, p_wb1);
    wconv_bf16<32, 64><<<128, 256>>>(w2, p_wb2);
    wconv_bf16<64, 64><<<256, 256>>>(w3, p_wb3);

    gs_kernel<<<dim3(H_, NIMG), W_>>>(x, nam);

    // convs: implicit GEMM on tensor cores
    conv_wmma<64, 32, 256, 128, 2><<<dim3(64, NIMG), 256>>>(p_neigh, p_wb1, b1, p_c1);
    conv_wmma<32, 64, 128,  64, 4><<<dim3(16, NIMG), 256>>>(p_c1,    p_wb2, b2, p_c2);
    conv_wmma<64, 64,  64,  32, 8><<<dim3( 4, NIMG), 256>>>(p_c2,    p_wb3, b3, p_c3);

    pool_kernel<<<NIMG, 256>>>();
    keys_kernel<<<NIMG, 256>>>(kf1w, kf1b, kf2w, kf2b, kf3w, kf3b);
    qry_kernel<<<B_, 256>>>(qf1w, qf1b, qf2w, qf2b, qf3w, qf3b, aw, ab);
    attn_kernel<<<B_, 160>>>();
    final_kernel<<<(B_*CIN*H_*W_/4)/256, 256>>>((float*)d_out);
}

// round 9
// speedup vs baseline: 1.5615x; 1.0868x over previous
#include <cuda_runtime.h>
#include <cuda_bf16.h>
#include <mma.h>
#include <math.h>

using namespace nvcuda;

#define NIMG 20
#define B_ 4
#define L_ 5
#define CIN 64
#define H_ 256
#define W_ 128

// ---------------- scratch (alloc-free rule: __device__ globals) ----------------
__device__ float g_neigh[(size_t)NIMG*CIN*H_*W_];   // 167.8 MB
__device__ float g_c1[(size_t)NIMG*32*128*64];      // raw conv1 out (pre bias/relu)
__device__ float g_c2[(size_t)NIMG*64*64*32];       // raw conv2 out
__device__ float g_c3[(size_t)NIMG*64*32*16];       // raw conv3 out
__device__ float g_pool[NIMG*64];
__device__ float g_keys[NIMG*256];
__device__ float g_q[B_*256];
__device__ float g_attn[B_*L_];
// bf16 weight matrices, layout [K][OC] with k = ic*16 + ky*4 + kx
__device__ __nv_bfloat16 g_wb1[1024*32];
__device__ __nv_bfloat16 g_wb2[512*64];
__device__ __nv_bfloat16 g_wb3[1024*64];

// ---------------- 1) affine grid + bilinear sample (zero pad) ----------------
__global__ void gs_kernel(const float* __restrict__ x, const float* __restrict__ nam) {
    int w   = threadIdx.x;      // 0..127
    int h   = blockIdx.x;       // 0..255
    int img = blockIdx.y;       // 0..19
    int b = img / L_, n = img % L_;
    const float* th = nam + ((size_t)b*L_*L_ + n)*6;   // tmats = nam[:,0] -> nam[b,0,n]
    float t0 = th[0], t1 = th[1], t2 = th[2];
    float t3 = th[3], t4 = th[4], t5 = th[5];

    float gx = (w + 0.5f)*(2.0f/W_) - 1.0f;
    float gy = (h + 0.5f)*(2.0f/H_) - 1.0f;
    float sx = t0*gx + t1*gy + t2;
    float sy = t3*gx + t4*gy + t5;
    float fx = ((sx + 1.0f)*W_ - 1.0f)*0.5f;
    float fy = ((sy + 1.0f)*H_ - 1.0f)*0.5f;
    float x0f = floorf(fx), y0f = floorf(fy);
    int ix0 = (int)x0f, iy0 = (int)y0f;
    int ix1 = ix0 + 1,  iy1 = iy0 + 1;
    float wx1 = fx - x0f, wy1 = fy - y0f;
    float wx0 = 1.0f - wx1, wy0 = 1.0f - wy1;

    bool vx0 = (ix0 >= 0) & (ix0 < W_);
    bool vx1 = (ix1 >= 0) & (ix1 < W_);
    bool vy0 = (iy0 >= 0) & (iy0 < H_);
    bool vy1 = (iy1 >= 0) & (iy1 < H_);
    int cx0 = min(max(ix0, 0), W_-1), cx1 = min(max(ix1, 0), W_-1);
    int cy0 = min(max(iy0, 0), H_-1), cy1 = min(max(iy1, 0), H_-1);

    float w00 = wx0*wy0*((vx0 & vy0) ? 1.0f : 0.0f);
    float w10 = wx1*wy0*((vx1 & vy0) ? 1.0f : 0.0f);
    float w01 = wx0*wy1*((vx0 & vy1) ? 1.0f : 0.0f);
    float w11 = wx1*wy1*((vx1 & vy1) ? 1.0f : 0.0f);

    int o00 = cy0*W_ + cx0, o10 = cy0*W_ + cx1;
    int o01 = cy1*W_ + cx0, o11 = cy1*W_ + cx1;

    const float* base = x + (size_t)img*CIN*H_*W_;
    float* outp = g_neigh + (size_t)img*CIN*H_*W_ + h*W_ + w;
    #pragma unroll 4
    for (int c = 0; c < CIN; c++) {
        const float* pc = base + (size_t)c*H_*W_;
        float v = w00*pc[o00] + w10*pc[o10] + w01*pc[o01] + w11*pc[o11];
        outp[(size_t)c*H_*W_] = v;
    }
}

// ---------------- weight f32 (OC,IC,4,4) -> bf16 [K][OC], k=(ic,ky,kx) ----------------
template<int IC, int OC>
__global__ void wconv_bf16(const float* __restrict__ w, __nv_bfloat16* __restrict__ wb) {
    int i = blockIdx.x*256 + threadIdx.x;          // over K*OC
    if (i >= IC*16*OC) return;
    int k = i / OC, oc = i % OC;
    int ic = k >> 4, t = k & 15;
    wb[i] = __float2bfloat16(w[((size_t)oc*IC + ic)*16 + t]);
}

// ---------------- conv 4x4 stride2 pad1, WMMA bf16 implicit GEMM -----------------
// Writes RAW pre-bias/pre-relu output. Consumer applies relu(raw + in_bias) when
// staging (APPLY_IN=true); zero-halo stays exactly 0 (pad applies to post-relu map).
// Group-staged: ICC=4 input channels per sync-group (3 syncs / 4 ic).
// Direct col-major fragment store: m = oh*OW+ow is linear in the spatial plane.
template<int IC, int OC, int IH, int IW, int TOH, bool APPLY_IN>
__global__ void __launch_bounds__(256) conv_wmma(const float* __restrict__ in,
                                                 const float* __restrict__ in_bias,
                                                 const __nv_bfloat16* __restrict__ wb,
                                                 float* __restrict__ out) {
    constexpr int OH = IH/2, OW = IW/2;
    constexpr int ROWS = 2*TOH + 2;
    constexpr int SW = IW + 2;
    constexpr int ICC = 4;
    static_assert(TOH*OW == 128, "M tile must be 128");
    static_assert(IC % ICC == 0, "IC divisible by ICC");

    __shared__ float s_rows[ICC][ROWS][SW];
    __shared__ __align__(32) __nv_bfloat16 s_a[ICC][128][16];

    int img = blockIdx.y;
    int oh0 = blockIdx.x * TOH;
    int tid = threadIdx.x;
    int wid = tid >> 5;

    wmma::fragment<wmma::accumulator, 16,16,16, float> acc[OC/16];
    #pragma unroll
    for (int j = 0; j < OC/16; j++) wmma::fill_fragment(acc[j], 0.0f);

    for (int icb = 0; icb < IC; icb += ICC) {
        __syncthreads();   // previous group's s_rows/s_a fully consumed
        // stage ICC channel row-windows (zero halo; optional bias+relu on loads)
        for (int i = tid; i < ICC*ROWS*SW; i += 256) {
            int icl = i / (ROWS*SW); int rem = i % (ROWS*SW);
            int r = rem / SW, c = rem % SW;
            int iy = 2*oh0 - 1 + r, ix = c - 1;
            float v = 0.0f;
            if (iy >= 0 && iy < IH && ix >= 0 && ix < IW) {
                v = in[(((size_t)img*IC + icb + icl)*IH + iy)*IW + ix];
                if (APPLY_IN) v = fmaxf(v + in_bias[icb + icl], 0.0f);
            }
            s_rows[icl][r][c] = v;
        }
        __syncthreads();
        // build A chunks for the whole group: [icl][128][16], k = ky*4+kx
        for (int i = tid; i < ICC*128*16; i += 256) {
            int icl = i >> 11; int rem = i & 2047;
            int m = rem >> 4, k = rem & 15;
            int ky = k >> 2, kx = k & 3;
            int ohl = m / OW, ow = m % OW;
            s_a[icl][m][k] = __float2bfloat16(s_rows[icl][2*ohl + ky][2*ow + kx]);
        }
        __syncthreads();
        #pragma unroll
        for (int icl = 0; icl < ICC; icl++) {
            wmma::fragment<wmma::matrix_a, 16,16,16, __nv_bfloat16, wmma::row_major> fa;
            wmma::load_matrix_sync(fa, &s_a[icl][wid*16][0], 16);
            #pragma unroll
            for (int j = 0; j < OC/16; j++) {
                wmma::fragment<wmma::matrix_b, 16,16,16, __nv_bfloat16, wmma::row_major> fb;
                wmma::load_matrix_sync(fb, wb + ((size_t)(icb + icl)*16)*OC + j*16, OC);
                wmma::mma_sync(acc[j], fa, fb, acc[j]);
            }
        }
    }

    // direct store: element (i, j') -> spatial oh0*OW + wid*16 + i, channel j*16+j'
    #pragma unroll
    for (int j = 0; j < OC/16; j++) {
        float* basep = out + (((size_t)img*OC + j*16)*OH + oh0)*OW + wid*16;
        wmma::store_matrix_sync(basep, acc[j], OH*OW, wmma::mem_col_major);
    }
}

// ---------------- 3) spatial mean pool of relu(c3 + b3) over 32x16=512 ----------
__global__ void pool_kernel(const float* __restrict__ b3) {
    int img = blockIdx.x;
    int t = threadIdx.x;            // 256
    int c = t >> 2, q = t & 3;
    float bc = b3[c];
    const float* p = g_c3 + ((size_t)img*64 + c)*512 + q*128;
    float s = 0.0f;
    for (int i = 0; i < 128; i++) s += fmaxf(p[i] + bc, 0.0f);
    __shared__ float sh[256];
    sh[t] = s;
    __syncthreads();
    if (q == 0)
        g_pool[img*64 + c] = (sh[t] + sh[t+1] + sh[t+2] + sh[t+3]) * (1.0f/512.0f);
}

// ---------------- 4) key MLP: 64->256->128->256 ----------------
__global__ void keys_kernel(const float* __restrict__ f1w, const float* __restrict__ f1b,
                            const float* __restrict__ f2w, const float* __restrict__ f2b,
                            const float* __restrict__ f3w, const float* __restrict__ f3b) {
    int img = blockIdx.x;
    int t = threadIdx.x;            // 256
    __shared__ float pooled[64], h1[256], h2[128];
    if (t < 64) pooled[t] = g_pool[img*64 + t];
    __syncthreads();
    {
        float s = f1b[t];
        const float* wr = f1w + (size_t)t*64;
        #pragma unroll 8
        for (int k = 0; k < 64; k++) s += pooled[k]*wr[k];
        h1[t] = fmaxf(s, 0.0f);
    }
    __syncthreads();
    if (t < 128) {
        float s = f2b[t];
        const float* wr = f2w + (size_t)t*256;
        #pragma unroll 8
        for (int k = 0; k < 256; k++) s += h1[k]*wr[k];
        h2[t] = fmaxf(s, 0.0f);
    }
    __syncthreads();
    {
        float s = f3b[t];
        const float* wr = f3w + (size_t)t*128;
        #pragma unroll 8
        for (int k = 0; k < 128; k++) s += h2[k]*wr[k];
        g_keys[img*256 + t] = s;
    }
}

// ---------------- 5) query MLP (img b*5): 64->256->128->32, then q = A qry + b ----------------
__global__ void qry_kernel(const float* __restrict__ f1w, const float* __restrict__ f1b,
                           const float* __restrict__ f2w, const float* __restrict__ f2b,
                           const float* __restrict__ f3w, const float* __restrict__ f3b,
                           const float* __restrict__ aw,  const float* __restrict__ ab) {
    int b = blockIdx.x;
    int img = b * L_;
    int t = threadIdx.x;            // 256
    __shared__ float pooled[64], h1[256], h2[128], qv[32];
    if (t < 64) pooled[t] = g_pool[img*64 + t];
    __syncthreads();
    {
        float s = f1b[t];
        const float* wr = f1w + (size_t)t*64;
        #pragma unroll 8
        for (int k = 0; k < 64; k++) s += pooled[k]*wr[k];
        h1[t] = fmaxf(s, 0.0f);
    }
    __syncthreads();
    if (t < 128) {
        float s = f2b[t];
        const float* wr = f2w + (size_t)t*256;
        #pragma unroll 8
        for (int k = 0; k < 256; k++) s += h1[k]*wr[k];
        h2[t] = fmaxf(s, 0.0f);
    }
    __syncthreads();
    if (t < 32) {
        float s = f3b[t];
        const float* wr = f3w + (size_t)t*128;
        #pragma unroll 8
        for (int k = 0; k < 128; k++) s += h2[k]*wr[k];
        qv[t] = s;   // no relu on last layer
    }
    __syncthreads();
    {
        float s = ab[t];
        const float* wr = aw + (size_t)t*32;
        #pragma unroll 8
        for (int k = 0; k < 32; k++) s += qv[k]*wr[k];
        g_q[b*256 + t] = s;
    }
}

// ---------------- 6) attention logits + softmax over L=5 ----------------
__global__ void attn_kernel() {
    int b = blockIdx.x;
    int t = threadIdx.x;            // 160 = 5 warps
    int n = t >> 5, lane = t & 31;
    __shared__ float logits[L_];
    const float* kp = g_keys + ((size_t)b*L_ + n)*256;
    const float* qp = g_q + b*256;
    float s = 0.0f;
    for (int k = lane; k < 256; k += 32) s += kp[k]*qp[k];
    #pragma unroll
    for (int o = 16; o; o >>= 1) s += __shfl_xor_sync(0xffffffff, s, o);
    if (lane == 0) logits[n] = s;
    __syncthreads();
    if (t == 0) {
        float m = logits[0];
        #pragma unroll
        for (int i = 1; i < L_; i++) m = fmaxf(m, logits[i]);
        float e[L_], sum = 0.0f;
        #pragma unroll
        for (int i = 0; i < L_; i++) { e[i] = expf(logits[i] - m); sum += e[i]; }
        #pragma unroll
        for (int i = 0; i < L_; i++) g_attn[b*L_ + i] = e[i] / sum;
    }
}

// ---------------- 7) out[b] = sum_n attn[b,n] * neigh[b,n] ----------------
__global__ void final_kernel(float* __restrict__ out) {
    size_t i = (size_t)blockIdx.x * blockDim.x + threadIdx.x;   // float4 index
    const size_t perimg4 = (size_t)CIN*H_*W_/4;                 // 524288
    int b = (int)(i / perimg4);
    size_t inner = i - (size_t)b*perimg4;
    const float4* nb = (const float4*)g_neigh;
    float a0 = g_attn[b*L_+0], a1 = g_attn[b*L_+1], a2 = g_attn[b*L_+2],
          a3 = g_attn[b*L_+3], a4 = g_attn[b*L_+4];
    float4 v0 = nb[((size_t)(b*L_+0))*perimg4 + inner];
    float4 v1 = nb[((size_t)(b*L_+1))*perimg4 + inner];
    float4 v2 = nb[((size_t)(b*L_+2))*perimg4 + inner];
    float4 v3 = nb[((size_t)(b*L_+3))*perimg4 + inner];
    float4 v4 = nb[((size_t)(b*L_+4))*perimg4 + inner];
    float4 r;
    r.x = a0*v0.x + a1*v1.x + a2*v2.x + a3*v3.x + a4*v4.x;
    r.y = a0*v0.y + a1*v1.y + a2*v2.y + a3*v3.y + a4*v4.y;
    r.z = a0*v0.z + a1*v1.z + a2*v2.z + a3*v3.z + a4*v4.z;
    r.w = a0*v0.w + a1*v1.w + a2*v2.w + a3*v3.w + a4*v4.w;
    ((float4*)out)[i] = r;
}

// ---------------- launch ----------------
extern "C" void kernel_launch(void* const* d_in, const int* in_sizes, int n_in,
                              void* d_out, int out_size) {
    const float* x    = (const float*)d_in[0];
    // d_in[1] = record_len (unused: always L)
    const float* nam  = (const float*)d_in[2];
    const float* w1   = (const float*)d_in[3];
    const float* b1   = (const float*)d_in[4];
    const float* w2   = (const float*)d_in[5];
    const float* b2   = (const float*)d_in[6];
    const float* w3   = (const float*)d_in[7];
    const float* b3   = (const float*)d_in[8];
    const float* kf1w = (const float*)d_in[9];
    const float* kf1b = (const float*)d_in[10];
    const float* kf2w = (const float*)d_in[11];
    const float* kf2b = (const float*)d_in[12];
    const float* kf3w = (const float*)d_in[13];
    const float* kf3b = (const float*)d_in[14];
    const float* qf1w = (const float*)d_in[15];
    const float* qf1b = (const float*)d_in[16];
    const float* qf2w = (const float*)d_in[17];
    const float* qf2b = (const float*)d_in[18];
    const float* qf3w = (const float*)d_in[19];
    const float* qf3b = (const float*)d_in[20];
    const float* aw   = (const float*)d_in[21];
    const float* ab   = (const float*)d_in[22];

    float *p_neigh, *p_c1, *p_c2, *p_c3;
    __nv_bfloat16 *p_wb1, *p_wb2, *p_wb3;
    cudaGetSymbolAddress((void**)&p_neigh, g_neigh);
    cudaGetSymbolAddress((void**)&p_c1, g_c1);
    cudaGetSymbolAddress((void**)&p_c2, g_c2);
    cudaGetSymbolAddress((void**)&p_c3, g_c3);
    cudaGetSymbolAddress((void**)&p_wb1, g_wb1);
    cudaGetSymbolAddress((void**)&p_wb2, g_wb2);
    cudaGetSymbolAddress((void**)&p_wb3, g_wb3);

    // weight conversion (tiny)
    wconv_bf16<64, 32><<<128, 256>>>(w1, p_wb1);
    wconv_bf16<32, 64><<<128, 256>>>(w2, p_wb2);
    wconv_bf16<64, 64><<<256, 256>>>(w3, p_wb3);

    gs_kernel<<<dim3(H_, NIMG), W_>>>(x, nam);

    // convs: implicit GEMM on tensor cores, raw outputs, consumer-side bias+relu
    conv_wmma<64, 32, 256, 128, 2, false><<<dim3(64, NIMG), 256>>>(p_neigh, nullptr, p_wb1, p_c1);
    conv_wmma<32, 64, 128,  64, 4, true ><<<dim3(16, NIMG), 256>>>(p_c1,    b1,      p_wb2, p_c2);
    conv_wmma<64, 64,  64,  32, 8, true ><<<dim3( 4, NIMG), 256>>>(p_c2,    b2,      p_wb3, p_c3);

    pool_kernel<<<NIMG, 256>>>(b3);
    keys_kernel<<<NIMG, 256>>>(kf1w, kf1b, kf2w, kf2b, kf3w, kf3b);
    qry_kernel<<<B_, 256>>>(qf1w, qf1b, qf2w, qf2b, qf3w, qf3b, aw, ab);
    attn_kernel<<<B_, 160>>>();
    final_kernel<<<(B_*CIN*H_*W_/4)/256, 256>>>((float*)d_out);
}

// round 16
// speedup vs baseline: 1.8180x; 1.1643x over previous
#include <cuda_runtime.h>
#include <cuda_bf16.h>
#include <mma.h>
#include <math.h>

using namespace nvcuda;

#define NIMG 20
#define B_ 4
#define L_ 5
#define CIN 64
#define H_ 256
#define W_ 128

// ---------------- scratch (alloc-free rule: __device__ globals) ----------------
__device__ float g_neigh[(size_t)NIMG*CIN*H_*W_];   // 167.8 MB
__device__ float g_c1[(size_t)NIMG*32*128*64];      // raw conv1 out (pre bias/relu)
__device__ float g_c2[(size_t)NIMG*64*64*32];       // raw conv2 out
__device__ float g_c3[(size_t)NIMG*64*32*16];      // raw conv3 out
__device__ float g_pool[NIMG*64];
__device__ float g_keys[NIMG*256];
__device__ float g_q[B_*256];
__device__ float g_attn[B_*L_];
// bf16 weight matrices, layout [K][OC] with k = ic*16 + ky*4 + kx
__device__ __nv_bfloat16 g_wb1[1024*32];
__device__ __nv_bfloat16 g_wb2[512*64];
__device__ __nv_bfloat16 g_wb3[1024*64];

// ---------------- 0) all weight casts in ONE launch (for profile ordering) -----
__global__ void wcast_all(const float* __restrict__ w1, const float* __restrict__ w2,
                          const float* __restrict__ w3) {
    int i = blockIdx.x*256 + threadIdx.x;
    if (i < 32768) {                       // conv1: [K=1024][OC=32] from [32][1024]
        int k = i >> 5, oc = i & 31;
        g_wb1[i] = __float2bfloat16(w1[oc*1024 + k]);
    } else if (i < 65536) {                // conv2: [K=512][OC=64] from [64][512]
        int j = i - 32768;
        int k = j >> 6, oc = j & 63;
        g_wb2[j] = __float2bfloat16(w2[oc*512 + k]);
    } else if (i < 131072) {               // conv3: [K=1024][OC=64] from [64][1024]
        int j = i - 65536;
        int k = j >> 6, oc = j & 63;
        g_wb3[j] = __float2bfloat16(w3[oc*1024 + k]);
    }
}

// ---------------- 1) affine grid + bilinear sample (zero pad) ----------------
__global__ void gs_kernel(const float* __restrict__ x, const float* __restrict__ nam,
                          int img0) {
    int w   = threadIdx.x;      // 0..127
    int h   = blockIdx.x;       // 0..255
    int img = blockIdx.y + img0;
    int b = img / L_, n = img % L_;
    const float* th = nam + ((size_t)b*L_*L_ + n)*6;   // tmats = nam[:,0] -> nam[b,0,n]
    float t0 = th[0], t1 = th[1], t2 = th[2];
    float t3 = th[3], t4 = th[4], t5 = th[5];

    float gx = (w + 0.5f)*(2.0f/W_) - 1.0f;
    float gy = (h + 0.5f)*(2.0f/H_) - 1.0f;
    float sx = t0*gx + t1*gy + t2;
    float sy = t3*gx + t4*gy + t5;
    float fx = ((sx + 1.0f)*W_ - 1.0f)*0.5f;
    float fy = ((sy + 1.0f)*H_ - 1.0f)*0.5f;
    float x0f = floorf(fx), y0f = floorf(fy);
    int ix0 = (int)x0f, iy0 = (int)y0f;
    int ix1 = ix0 + 1,  iy1 = iy0 + 1;
    float wx1 = fx - x0f, wy1 = fy - y0f;
    float wx0 = 1.0f - wx1, wy0 = 1.0f - wy1;

    bool vx0 = (ix0 >= 0) & (ix0 < W_);
    bool vx1 = (ix1 >= 0) & (ix1 < W_);
    bool vy0 = (iy0 >= 0) & (iy0 < H_);
    bool vy1 = (iy1 >= 0) & (iy1 < H_);
    int cx0 = min(max(ix0, 0), W_-1), cx1 = min(max(ix1, 0), W_-1);
    int cy0 = min(max(iy0, 0), H_-1), cy1 = min(max(iy1, 0), H_-1);

    float w00 = wx0*wy0*((vx0 & vy0) ? 1.0f : 0.0f);
    float w10 = wx1*wy0*((vx1 & vy0) ? 1.0f : 0.0f);
    float w01 = wx0*wy1*((vx0 & vy1) ? 1.0f : 0.0f);
    float w11 = wx1*wy1*((vx1 & vy1) ? 1.0f : 0.0f);

    int o00 = cy0*W_ + cx0, o10 = cy0*W_ + cx1;
    int o01 = cy1*W_ + cx0, o11 = cy1*W_ + cx1;

    const float* base = x + (size_t)img*CIN*H_*W_;
    float* outp = g_neigh + (size_t)img*CIN*H_*W_ + h*W_ + w;
    #pragma unroll 4
    for (int c = 0; c < CIN; c++) {
        const float* pc = base + (size_t)c*H_*W_;
        float v = w00*pc[o00] + w10*pc[o10] + w01*pc[o01] + w11*pc[o11];
        outp[(size_t)c*H_*W_] = v;
    }
}

// ---------------- conv 4x4 stride2 pad1, WMMA bf16 implicit GEMM -----------------
// Raw pre-bias/pre-relu output; consumer applies relu(raw + in_bias) when staging
// (zero-halo stays exactly 0: pad applies to the post-relu map).
// Group-staged ICC=4 channels; B chunk staged in smem (no global fragment loads);
// s_a/s_b rows padded to break ldmatrix bank conflicts; direct col-major store.
template<int IC, int OC, int IH, int IW, int TOH, bool APPLY_IN>
__global__ void __launch_bounds__(256) conv_wmma(const float* __restrict__ in,
                                                 const float* __restrict__ in_bias,
                                                 const __nv_bfloat16* __restrict__ wb,
                                                 float* __restrict__ out) {
    constexpr int OH = IH/2, OW = IW/2;
    constexpr int ROWS = 2*TOH + 2;
    constexpr int SW = IW + 2;
    constexpr int ICC = 4;
    constexpr int AP = 24;       // padded A row (elements)
    constexpr int BP = OC + 8;   // padded B row (elements)
    static_assert(TOH*OW == 128, "M tile must be 128");
    static_assert(IC % ICC == 0, "IC divisible by ICC");

    __shared__ float s_rows[ICC][ROWS][SW];
    __shared__ __align__(32) __nv_bfloat16 s_a[ICC][128][AP];
    __shared__ __align__(32) __nv_bfloat16 s_b[ICC*16][BP];

    int img = blockIdx.y;
    int oh0 = blockIdx.x * TOH;
    int tid = threadIdx.x;
    int wid = tid >> 5;

    wmma::fragment<wmma::accumulator, 16,16,16, float> acc[OC/16];
    #pragma unroll
    for (int j = 0; j < OC/16; j++) wmma::fill_fragment(acc[j], 0.0f);

    for (int icb = 0; icb < IC; icb += ICC) {
        __syncthreads();   // previous group's buffers fully consumed
        // stage ICC channel row-windows (zero halo; optional bias+relu on loads)
        for (int i = tid; i < ICC*ROWS*SW; i += 256) {
            int icl = i / (ROWS*SW); int rem = i % (ROWS*SW);
            int r = rem / SW, c = rem % SW;
            int iy = 2*oh0 - 1 + r, ix = c - 1;
            float v = 0.0f;
            if (iy >= 0 && iy < IH && ix >= 0 && ix < IW) {
                v = in[(((size_t)img*IC + icb + icl)*IH + iy)*IW + ix];
                if (APPLY_IN) v = fmaxf(v + in_bias[icb + icl], 0.0f);
            }
            s_rows[icl][r][c] = v;
        }
        // stage B chunk [ICC*16][OC] (coalesced over oc)
        for (int i = tid; i < ICC*16*OC; i += 256) {
            int k = i / OC, oc = i % OC;
            s_b[k][oc] = wb[((size_t)icb*16 + k)*OC + oc];
        }
        __syncthreads();
        // build A chunks: [icl][128][16 of AP], k = ky*4+kx
        for (int i = tid; i < ICC*128*16; i += 256) {
            int icl = i >> 11; int rem = i & 2047;
            int m = rem >> 4, k = rem & 15;
            int ky = k >> 2, kx = k & 3;
            int ohl = m / OW, ow = m % OW;
            s_a[icl][m][k] = __float2bfloat16(s_rows[icl][2*ohl + ky][2*ow + kx]);
        }
        __syncthreads();
        #pragma unroll
        for (int icl = 0; icl < ICC; icl++) {
            wmma::fragment<wmma::matrix_a, 16,16,16, __nv_bfloat16, wmma::row_major> fa;
            wmma::load_matrix_sync(fa, &s_a[icl][wid*16][0], AP);
            #pragma unroll
            for (int j = 0; j < OC/16; j++) {
                wmma::fragment<wmma::matrix_b, 16,16,16, __nv_bfloat16, wmma::row_major> fb;
                wmma::load_matrix_sync(fb, &s_b[icl*16][j*16], BP);
                wmma::mma_sync(acc[j], fa, fb, acc[j]);
            }
        }
    }

    // direct store: element (i, j') -> spatial oh0*OW + wid*16 + i, channel j*16+j'
    #pragma unroll
    for (int j = 0; j < OC/16; j++) {
        float* basep = out + (((size_t)img*OC + j*16)*OH + oh0)*OW + wid*16;
        wmma::store_matrix_sync(basep, acc[j], OH*OW, wmma::mem_col_major);
    }
}

// ---------------- 3) spatial mean pool of relu(c3 + b3) over 32x16=512 ----------
__global__ void pool_kernel(const float* __restrict__ b3) {
    int img = blockIdx.x;
    int t = threadIdx.x;            // 256
    int c = t >> 2, q = t & 3;
    float bc = b3[c];
    const float* p = g_c3 + ((size_t)img*64 + c)*512 + q*128;
    float s = 0.0f;
    for (int i = 0; i < 128; i++) s += fmaxf(p[i] + bc, 0.0f);
    __shared__ float sh[256];
    sh[t] = s;
    __syncthreads();
    if (q == 0)
        g_pool[img*64 + c] = (sh[t] + sh[t+1] + sh[t+2] + sh[t+3]) * (1.0f/512.0f);
}

// ---------------- 4) key MLP: 64->256->128->256 ----------------
__global__ void keys_kernel(const float* __restrict__ f1w, const float* __restrict__ f1b,
                            const float* __restrict__ f2w, const float* __restrict__ f2b,
                            const float* __restrict__ f3w, const float* __restrict__ f3b) {
    int img = blockIdx.x;
    int t = threadIdx.x;            // 256
    __shared__ float pooled[64], h1[256], h2[128];
    if (t < 64) pooled[t] = g_pool[img*64 + t];
    __syncthreads();
    {
        float s = f1b[t];
        const float* wr = f1w + (size_t)t*64;
        #pragma unroll 8
        for (int k = 0; k < 64; k++) s += pooled[k]*wr[k];
        h1[t] = fmaxf(s, 0.0f);
    }
    __syncthreads();
    if (t < 128) {
        float s = f2b[t];
        const float* wr = f2w + (size_t)t*256;
        #pragma unroll 8
        for (int k = 0; k < 256; k++) s += h1[k]*wr[k];
        h2[t] = fmaxf(s, 0.0f);
    }
    __syncthreads();
    {
        float s = f3b[t];
        const float* wr = f3w + (size_t)t*128;
        #pragma unroll 8
        for (int k = 0; k < 128; k++) s += h2[k]*wr[k];
        g_keys[img*256 + t] = s;
    }
}

// ---------------- 5) query MLP (img b*5): 64->256->128->32, then q = A qry + b ---
__global__ void qry_kernel(const float* __restrict__ f1w, const float* __restrict__ f1b,
                           const float* __restrict__ f2w, const float* __restrict__ f2b,
                           const float* __restrict__ f3w, const float* __restrict__ f3b,
                           const float* __restrict__ aw,  const float* __restrict__ ab) {
    int b = blockIdx.x;
    int img = b * L_;
    int t = threadIdx.x;            // 256
    __shared__ float pooled[64], h1[256], h2[128], qv[32];
    if (t < 64) pooled[t] = g_pool[img*64 + t];
    __syncthreads();
    {
        float s = f1b[t];
        const float* wr = f1w + (size_t)t*64;
        #pragma unroll 8
        for (int k = 0; k < 64; k++) s += pooled[k]*wr[k];
        h1[t] = fmaxf(s, 0.0f);
    }
    __syncthreads();
    if (t < 128) {
        float s = f2b[t];
        const float* wr = f2w + (size_t)t*256;
        #pragma unroll 8
        for (int k = 0; k < 256; k++) s += h1[k]*wr[k];
        h2[t] = fmaxf(s, 0.0f);
    }
    __syncthreads();
    if (t < 32) {
        float s = f3b[t];
        const float* wr = f3w + (size_t)t*128;
        #pragma unroll 8
        for (int k = 0; k < 128; k++) s += h2[k]*wr[k];
        qv[t] = s;   // no relu on last layer
    }
    __syncthreads();
    {
        float s = ab[t];
        const float* wr = aw + (size_t)t*32;
        #pragma unroll 8
        for (int k = 0; k < 32; k++) s += qv[k]*wr[k];
        g_q[b*256 + t] = s;
    }
}

// ---------------- 6) attention logits + softmax over L=5 ----------------
__global__ void attn_kernel() {
    int b = blockIdx.x;
    int t = threadIdx.x;            // 160 = 5 warps
    int n = t >> 5, lane = t & 31;
    __shared__ float logits[L_];
    const float* kp = g_keys + ((size_t)b*L_ + n)*256;
    const float* qp = g_q + b*256;
    float s = 0.0f;
    for (int k = lane; k < 256; k += 32) s += kp[k]*qp[k];
    #pragma unroll
    for (int o = 16; o; o >>= 1) s += __shfl_xor_sync(0xffffffff, s, o);
    if (lane == 0) logits[n] = s;
    __syncthreads();
    if (t == 0) {
        float m = logits[0];
        #pragma unroll
        for (int i = 1; i < L_; i++) m = fmaxf(m, logits[i]);
        float e[L_], sum = 0.0f;
        #pragma unroll
        for (int i = 0; i < L_; i++) { e[i] = expf(logits[i] - m); sum += e[i]; }
        #pragma unroll
        for (int i = 0; i < L_; i++) g_attn[b*L_ + i] = e[i] / sum;
    }
}

// ---------------- 7) out[b] = sum_n attn[b,n] * neigh[b,n] ----------------
__global__ void final_kernel(float* __restrict__ out) {
    size_t i = (size_t)blockIdx.x * blockDim.x + threadIdx.x;   // float4 index
    const size_t perimg4 = (size_t)CIN*H_*W_/4;                 // 524288
    int b = (int)(i / perimg4);
    size_t inner = i - (size_t)b*perimg4;
    const float4* nb = (const float4*)g_neigh;
    float a0 = g_attn[b*L_+0], a1 = g_attn[b*L_+1], a2 = g_attn[b*L_+2],
          a3 = g_attn[b*L_+3], a4 = g_attn[b*L_+4];
    float4 v0 = nb[((size_t)(b*L_+0))*perimg4 + inner];
    float4 v1 = nb[((size_t)(b*L_+1))*perimg4 + inner];
    float4 v2 = nb[((size_t)(b*L_+2))*perimg4 + inner];
    float4 v3 = nb[((size_t)(b*L_+3))*perimg4 + inner];
    float4 v4 = nb[((size_t)(b*L_+4))*perimg4 + inner];
    float4 r;
    r.x = a0*v0.x + a1*v1.x + a2*v2.x + a3*v3.x + a4*v4.x;
    r.y = a0*v0.y + a1*v1.y + a2*v2.y + a3*v3.y + a4*v4.y;
    r.z = a0*v0.z + a1*v1.z + a2*v2.z + a3*v3.z + a4*v4.z;
    r.w = a0*v0.w + a1*v1.w + a2*v2.w + a3*v3.w + a4*v4.w;
    ((float4*)out)[i] = r;
}

// ---------------- launch ----------------
extern "C" void kernel_launch(void* const* d_in, const int* in_sizes, int n_in,
                              void* d_out, int out_size) {
    const float* x    = (const float*)d_in[0];
    // d_in[1] = record_len (unused: always L)
    const float* nam  = (const float*)d_in[2];
    const float* w1   = (const float*)d_in[3];
    const float* b1   = (const float*)d_in[4];
    const float* w2   = (const float*)d_in[5];
    const float* b2   = (const float*)d_in[6];
    const float* w3   = (const float*)d_in[7];
    const float* b3   = (const float*)d_in[8];
    const float* kf1w = (const float*)d_in[9];
    const float* kf1b = (const float*)d_in[10];
    const float* kf2w = (const float*)d_in[11];
    const float* kf2b = (const float*)d_in[12];
    const float* kf3w = (const float*)d_in[13];
    const float* kf3b = (const float*)d_in[14];
    const float* qf1w = (const float*)d_in[15];
    const float* qf1b = (const float*)d_in[16];
    const float* qf2w = (const float*)d_in[17];
    const float* qf2b = (const float*)d_in[18];
    const float* qf3w = (const float*)d_in[19];
    const float* qf3b = (const float*)d_in[20];
    const float* aw   = (const float*)d_in[21];
    const float* ab   = (const float*)d_in[22];

    float *p_neigh, *p_c1, *p_c2, *p_c3;
    __nv_bfloat16 *p_wb1, *p_wb2, *p_wb3;
    cudaGetSymbolAddress((void**)&p_neigh, g_neigh);
    cudaGetSymbolAddress((void**)&p_c1, g_c1);
    cudaGetSymbolAddress((void**)&p_c2, g_c2);
    cudaGetSymbolAddress((void**)&p_c3, g_c3);
    cudaGetSymbolAddress((void**)&p_wb1, g_wb1);
    cudaGetSymbolAddress((void**)&p_wb2, g_wb2);
    cudaGetSymbolAddress((void**)&p_wb3, g_wb3);

    // launch order chosen so conv1 is the 4th launch (profiled by ncu):
    wcast_all<<<512, 256>>>(w1, w2, w3);                        // 0
    gs_kernel<<<dim3(H_, 10), W_>>>(x, nam, 0);                 // 1
    gs_kernel<<<dim3(H_, 10), W_>>>(x, nam, 10);                // 2
    conv_wmma<64, 32, 256, 128, 2, false><<<dim3(64, NIMG), 256>>>(p_neigh, nullptr, p_wb1, p_c1);  // 3
    conv_wmma<32, 64, 128,  64, 4, true ><<<dim3(16, NIMG), 256>>>(p_c1,    b1,      p_wb2, p_c2);
    conv_wmma<64, 64,  64,  32, 8, true ><<<dim3( 4, NIMG), 256>>>(p_c2,    b2,      p_wb3, p_c3);

    pool_kernel<<<NIMG, 256>>>(b3);
    keys_kernel<<<NIMG, 256>>>(kf1w, kf1b, kf2w, kf2b, kf3w, kf3b);
    qry_kernel<<<B_, 256>>>(qf1w, qf1b, qf2w, qf2b, qf3w, qf3b, aw, ab);
    attn_kernel<<<B_, 160>>>();
    final_kernel<<<(B_*CIN*H_*W_/4)/256, 256>>>((float*)d_out);
}